// round 1
// baseline (speedup 1.0000x reference)
#include <cuda_runtime.h>
#include <cuda_bf16.h>
#include <cstdint>
#include <cstddef>

#define SEQ 2048
#define EMB 1024
#define HID 1024
#define G4  4096
#define VOC 50257

// ------------------------- device scratch -------------------------
__device__ __nv_bfloat16 g_xb[SEQ * EMB];            // bf16 embedded inputs
__device__ __nv_bfloat16 g_wih[G4 * EMB];            // bf16 W_ih
__device__ __nv_bfloat16 g_wout[(size_t)VOC * HID];  // bf16 W_out
__device__ __nv_bfloat16 g_hsb[SEQ * HID];           // bf16 hidden states
__device__ float g_xgates[(size_t)SEQ * G4];         // fp32 x@W_ih^T + b
__device__ float g_hs[SEQ * HID];                    // fp32 hidden states
__device__ float g_hbuf[2][HID];                     // double-buffered h
__device__ float g_bias[G4];                         // b_ih + b_hh
__device__ int   g_flags[128];                       // per-CTA step flags

// ------------------------- init -------------------------
__global__ void init_state_kernel() {
    int i = blockIdx.x * blockDim.x + threadIdx.x;
    if (i < 128) g_flags[i] = 0;
    if (i < HID) { g_hbuf[0][i] = 0.f; g_hbuf[1][i] = 0.f; }
}

__global__ void bias_sum_kernel(const float* __restrict__ b_ih,
                                const float* __restrict__ b_hh) {
    int i = blockIdx.x * blockDim.x + threadIdx.x;
    if (i < G4) g_bias[i] = b_ih[i] + b_hh[i];
}

// ------------------------- converts -------------------------
__global__ void cvt_wih_kernel(const float4* __restrict__ in) {
    int i = blockIdx.x * blockDim.x + threadIdx.x;    // n4 = G4*EMB/4
    if (i >= G4 * EMB / 4) return;
    float4 v = in[i];
    __nv_bfloat162* o = (__nv_bfloat162*)g_wih;
    o[2 * i]     = __floats2bfloat162_rn(v.x, v.y);
    o[2 * i + 1] = __floats2bfloat162_rn(v.z, v.w);
}

__global__ void cvt_wout_kernel(const float4* __restrict__ in) {
    int i = blockIdx.x * blockDim.x + threadIdx.x;    // n4 = VOC*HID/4
    if (i >= (int)((size_t)VOC * HID / 4)) return;
    float4 v = in[i];
    __nv_bfloat162* o = (__nv_bfloat162*)g_wout;
    o[2 * i]     = __floats2bfloat162_rn(v.x, v.y);
    o[2 * i + 1] = __floats2bfloat162_rn(v.z, v.w);
}

__global__ void cvt_hs_kernel() {
    int i = blockIdx.x * blockDim.x + threadIdx.x;    // n4 = SEQ*HID/4
    if (i >= SEQ * HID / 4) return;
    float4 v = ((const float4*)g_hs)[i];
    __nv_bfloat162* o = (__nv_bfloat162*)g_hsb;
    o[2 * i]     = __floats2bfloat162_rn(v.x, v.y);
    o[2 * i + 1] = __floats2bfloat162_rn(v.z, v.w);
}

__global__ void gather_emb_kernel(const int* __restrict__ seq,
                                  const float* __restrict__ emb) {
    int i = blockIdx.x * blockDim.x + threadIdx.x;    // n4 = SEQ*EMB/4
    if (i >= SEQ * EMB / 4) return;
    int t  = i >> 8;        // EMB/4 = 256 float4 per row
    int e4 = i & 255;
    float4 v = ((const float4*)(emb + (size_t)seq[t] * EMB))[e4];
    __nv_bfloat162* o = (__nv_bfloat162*)g_xb;
    o[2 * i]     = __floats2bfloat162_rn(v.x, v.y);
    o[2 * i + 1] = __floats2bfloat162_rn(v.z, v.w);
}

// ------------------------- bf16 mma GEMM: C[M,N] = A[M,K] @ B[N,K]^T + bias -------
#define GBM 128
#define GBN 64
#define GBK 32
#define GST 40   // smem row stride in bf16 (32 + 8 pad; 80B = 16B-aligned, conflict-free)

__device__ __forceinline__ void cp_async16(void* dst, const void* src) {
    uint32_t d = (uint32_t)__cvta_generic_to_shared(dst);
    asm volatile("cp.async.cg.shared.global [%0], [%1], 16;\n" :: "r"(d), "l"(src));
}
#define CP_COMMIT() asm volatile("cp.async.commit_group;\n" ::: "memory")
#define CP_WAIT0()  asm volatile("cp.async.wait_group 0;\n" ::: "memory")

__device__ __forceinline__ void mma_bf16(float* d, const uint32_t* a, const uint32_t* b) {
    asm volatile(
        "mma.sync.aligned.m16n8k16.row.col.f32.bf16.bf16.f32 "
        "{%0,%1,%2,%3}, {%4,%5,%6,%7}, {%8,%9}, {%0,%1,%2,%3};\n"
        : "+f"(d[0]), "+f"(d[1]), "+f"(d[2]), "+f"(d[3])
        : "r"(a[0]), "r"(a[1]), "r"(a[2]), "r"(a[3]), "r"(b[0]), "r"(b[1]));
}

__device__ __forceinline__ void gemm_core(
    const __nv_bfloat16* __restrict__ A,   // [M,K] row-major (M = gridDim.y*128)
    const __nv_bfloat16* __restrict__ B,   // [N,K] row-major
    const float* __restrict__ bias,        // [N]
    float* __restrict__ C,                 // [M,N]
    int N, int K)
{
    __shared__ __align__(16) __nv_bfloat16 As[2][GBM * GST];
    __shared__ __align__(16) __nv_bfloat16 Bs[2][GBN * GST];

    const int tid  = threadIdx.x;
    const int m0   = blockIdx.y * GBM;
    const int n0   = blockIdx.x * GBN;
    const int warp = tid >> 5, lane = tid & 31;
    const int wm = (warp >> 1) * 32;   // warp m-origin (0..96)
    const int wn = (warp & 1) * 32;    // warp n-origin (0 or 32)

    float acc[2][4][4];
#pragma unroll
    for (int a = 0; a < 2; a++)
#pragma unroll
        for (int b = 0; b < 4; b++)
#pragma unroll
            for (int q = 0; q < 4; q++) acc[a][b][q] = 0.f;

    const int nk = K / GBK;

    // stage loader
    auto load_stage = [&](int s, int k0) {
#pragma unroll
        for (int i = 0; i < 2; i++) {       // A: 512 x 16B chunks
            int id = tid + i * 256;
            int r = id >> 2, cc = id & 3;
            cp_async16(&As[s][r * GST + cc * 8],
                       A + (size_t)(m0 + r) * K + k0 + cc * 8);
        }
        {                                    // B: 256 x 16B chunks
            int r = tid >> 2, cc = tid & 3;
            int n = n0 + r; if (n >= N) n = N - 1;   // clamp; garbage cols never stored
            cp_async16(&Bs[s][r * GST + cc * 8],
                       B + (size_t)n * K + k0 + cc * 8);
        }
    };

    load_stage(0, 0);
    CP_COMMIT();

    for (int kt = 0; kt < nk; kt++) {
        CP_WAIT0();
        __syncthreads();
        int cur = kt & 1;
        if (kt + 1 < nk) { load_stage(cur ^ 1, (kt + 1) * GBK); CP_COMMIT(); }

#pragma unroll
        for (int kk = 0; kk < GBK; kk += 16) {
            uint32_t ra[2][4], rb[4][2];
#pragma unroll
            for (int tm = 0; tm < 2; tm++) {
                const __nv_bfloat16* ap =
                    &As[cur][(wm + tm * 16 + (lane >> 2)) * GST + kk + (lane & 3) * 2];
                ra[tm][0] = *(const uint32_t*)ap;
                ra[tm][1] = *(const uint32_t*)(ap + 8 * GST);
                ra[tm][2] = *(const uint32_t*)(ap + 8);
                ra[tm][3] = *(const uint32_t*)(ap + 8 * GST + 8);
            }
#pragma unroll
            for (int tn = 0; tn < 4; tn++) {
                const __nv_bfloat16* bp =
                    &Bs[cur][(wn + tn * 8 + (lane >> 2)) * GST + kk + (lane & 3) * 2];
                rb[tn][0] = *(const uint32_t*)bp;
                rb[tn][1] = *(const uint32_t*)(bp + 8);
            }
#pragma unroll
            for (int tm = 0; tm < 2; tm++)
#pragma unroll
                for (int tn = 0; tn < 4; tn++)
                    mma_bf16(acc[tm][tn], ra[tm], rb[tn]);
        }
    }

    // epilogue
#pragma unroll
    for (int tm = 0; tm < 2; tm++) {
#pragma unroll
        for (int tn = 0; tn < 4; tn++) {
            int r  = m0 + wm + tm * 16 + (lane >> 2);
            int cb = n0 + wn + tn * 8 + (lane & 3) * 2;
            if (cb < N) {
                C[(size_t)r * N + cb]       = acc[tm][tn][0] + bias[cb];
                C[(size_t)(r + 8) * N + cb] = acc[tm][tn][2] + bias[cb];
            }
            if (cb + 1 < N) {
                C[(size_t)r * N + cb + 1]       = acc[tm][tn][1] + bias[cb + 1];
                C[(size_t)(r + 8) * N + cb + 1] = acc[tm][tn][3] + bias[cb + 1];
            }
        }
    }
}

__global__ __launch_bounds__(256, 2) void gemm1_kernel() {
    gemm_core(g_xb, g_wih, g_bias, g_xgates, G4, EMB);
}
__global__ __launch_bounds__(256, 2) void gemm2_kernel(const float* __restrict__ b_out,
                                                       float* __restrict__ out) {
    gemm_core(g_hsb, g_wout, b_out, out, VOC, HID);
}

// ------------------------- persistent LSTM -------------------------
// 128 CTAs x 512 threads; CTA b owns h indices j = b*8 + r, r in [0,8).
// SMEM: W_hh rows for its 32 gate rows (fp32, 128KB) + h (4KB) + gate partials.
#define LSTM_NCTA    128
#define LSTM_THREADS 512
#define LSTM_SMEM    ((32 * 1024 + 1024 + 32) * 4)

__global__ __launch_bounds__(LSTM_THREADS, 1)
void lstm_kernel(const float* __restrict__ W_hh) {
    extern __shared__ float smf[];
    float* sWhh = smf;                 // [32][1024], row rr = gate*8 + r
    float* sh   = smf + 32 * 1024;     // [1024]
    float* sg   = sh + 1024;           // [32] gate preacts (recurrent part)

    const int tid = threadIdx.x, b = blockIdx.x;
    const int lane = tid & 31, w = tid >> 5;

    // load this CTA's 32 W_hh rows into SMEM (float4)
    for (int i = tid; i < 32 * 256; i += LSTM_THREADS) {
        int rr = i >> 8, kk = i & 255;
        int grow = (rr >> 3) * 1024 + b * 8 + (rr & 7);
        ((float4*)sWhh)[rr * 256 + kk] =
            ((const float4*)(W_hh + (size_t)grow * HID))[kk];
    }
    float c_reg = 0.f;   // thread r<8 carries c for j = b*8 + r
    __syncthreads();

    volatile int* vflags = g_flags;

    for (int t = 0; t < SEQ; t++) {
        // prefetch x-gate contributions (independent of h) before polling
        float xg0 = 0.f, xg1 = 0.f, xg2 = 0.f, xg3 = 0.f;
        if (tid < 8) {
            const float* xgp = g_xgates + (size_t)t * G4 + b * 8 + tid;
            xg0 = xgp[0]; xg1 = xgp[1024]; xg2 = xgp[2048]; xg3 = xgp[3072];
        }
        // wait for all CTAs to finish step t-1
        if (t > 0) {
            if (tid < LSTM_NCTA) { while (vflags[tid] < t) { } }
            __threadfence();
        }
        __syncthreads();

        // load current h (L1-bypassing: other SMs wrote it)
        const float* hg = g_hbuf[t & 1];
        for (int i = tid; i < HID; i += LSTM_THREADS) sh[i] = __ldcv(&hg[i]);
        __syncthreads();

        // recurrent dot products: warp w computes rows 2w, 2w+1
        {
            const float* w0 = sWhh + (2 * w) * 1024;
            const float* w1 = w0 + 1024;
            float s0 = 0.f, s1 = 0.f;
#pragma unroll
            for (int kk = 0; kk < 8; kk++) {
                int k = lane * 4 + kk * 128;
                float4 hv = *(const float4*)(sh + k);
                float4 a0 = *(const float4*)(w0 + k);
                float4 a1 = *(const float4*)(w1 + k);
                s0 = fmaf(a0.x, hv.x, s0); s0 = fmaf(a0.y, hv.y, s0);
                s0 = fmaf(a0.z, hv.z, s0); s0 = fmaf(a0.w, hv.w, s0);
                s1 = fmaf(a1.x, hv.x, s1); s1 = fmaf(a1.y, hv.y, s1);
                s1 = fmaf(a1.z, hv.z, s1); s1 = fmaf(a1.w, hv.w, s1);
            }
#pragma unroll
            for (int o = 16; o > 0; o >>= 1) {
                s0 += __shfl_xor_sync(0xffffffffu, s0, o);
                s1 += __shfl_xor_sync(0xffffffffu, s1, o);
            }
            if (lane == 0) { sg[2 * w] = s0; sg[2 * w + 1] = s1; }
        }
        __syncthreads();

        // elementwise gate update for the 8 owned h indices
        if (tid < 8) {
            int j = b * 8 + tid;
            float gi = sg[0 * 8 + tid] + xg0;
            float gf = sg[1 * 8 + tid] + xg1;
            float gg = sg[2 * 8 + tid] + xg2;
            float go = sg[3 * 8 + tid] + xg3;
            float i_ = 1.f / (1.f + expf(-gi));
            float f_ = 1.f / (1.f + expf(-gf));
            float g_ = tanhf(gg);
            float o_ = 1.f / (1.f + expf(-go));
            c_reg = f_ * c_reg + i_ * g_;
            float h_ = o_ * tanhf(c_reg);
            g_hbuf[(t + 1) & 1][j] = h_;
            g_hs[(size_t)t * HID + j] = h_;
        }
        __threadfence();
        __syncthreads();
        if (tid == 0) ((volatile int*)g_flags)[b] = t + 1;
    }
}

// ------------------------- row log-softmax (in place) -------------------------
__global__ void logsoftmax_kernel(float* __restrict__ out, int N) {
    const int row = blockIdx.x;
    float* p = out + (size_t)row * N;
    const int tid = threadIdx.x, lane = tid & 31, wid = tid >> 5;
    const int nt = blockDim.x, nw = nt >> 5;
    __shared__ float red[16];

    float m = -3.4e38f;
    for (int i = tid; i < N; i += nt) m = fmaxf(m, p[i]);
#pragma unroll
    for (int o = 16; o > 0; o >>= 1) m = fmaxf(m, __shfl_xor_sync(0xffffffffu, m, o));
    if (lane == 0) red[wid] = m;
    __syncthreads();
    if (tid == 0) {
        float v = red[0];
        for (int i = 1; i < nw; i++) v = fmaxf(v, red[i]);
        red[0] = v;
    }
    __syncthreads();
    m = red[0];
    __syncthreads();

    float s = 0.f;
    for (int i = tid; i < N; i += nt) s += __expf(p[i] - m);
#pragma unroll
    for (int o = 16; o > 0; o >>= 1) s += __shfl_xor_sync(0xffffffffu, s, o);
    if (lane == 0) red[wid] = s;
    __syncthreads();
    if (tid == 0) {
        float v = 0.f;
        for (int i = 0; i < nw; i++) v += red[i];
        red[0] = v;
    }
    __syncthreads();
    float lse = m + logf(red[0]);

    for (int i = tid; i < N; i += nt) p[i] -= lse;
}

// ------------------------- launch -------------------------
extern "C" void kernel_launch(void* const* d_in, const int* in_sizes, int n_in,
                              void* d_out, int out_size) {
    const int*   seq   = (const int*)d_in[0];
    const float* emb   = (const float*)d_in[1];
    const float* W_ih  = (const float*)d_in[2];
    const float* W_hh  = (const float*)d_in[3];
    const float* b_ih  = (const float*)d_in[4];
    const float* b_hh  = (const float*)d_in[5];
    const float* W_out = (const float*)d_in[6];
    const float* b_out = (const float*)d_in[7];
    float* out = (float*)d_out;

    (void)in_sizes; (void)n_in; (void)out_size;

    cudaFuncSetAttribute(lstm_kernel,
                         cudaFuncAttributeMaxDynamicSharedMemorySize, LSTM_SMEM);

    init_state_kernel<<<4, 256>>>();
    bias_sum_kernel<<<16, 256>>>(b_ih, b_hh);
    cvt_wih_kernel<<<(G4 * EMB / 4) / 256, 256>>>((const float4*)W_ih);
    cvt_wout_kernel<<<(int)(((size_t)VOC * HID / 4 + 255) / 256), 256>>>((const float4*)W_out);
    gather_emb_kernel<<<(SEQ * EMB / 4) / 256, 256>>>(seq, emb);

    {   // x_gates = xb @ W_ih^T + (b_ih + b_hh)
        dim3 grid(G4 / GBN, SEQ / GBM);
        gemm1_kernel<<<grid, 256>>>();
    }

    lstm_kernel<<<LSTM_NCTA, LSTM_THREADS, LSTM_SMEM>>>(W_hh);

    cvt_hs_kernel<<<(SEQ * HID / 4) / 256, 256>>>();

    {   // logits = hs @ W_out^T + b_out  -> d_out
        dim3 grid((VOC + GBN - 1) / GBN, SEQ / GBM);
        gemm2_kernel<<<grid, 256>>>(b_out, out);
    }

    logsoftmax_kernel<<<SEQ, 512>>>(out, VOC);
}

// round 3
// speedup vs baseline: 1.6071x; 1.6071x over previous
#include <cuda_runtime.h>
#include <cuda_bf16.h>
#include <cstdint>
#include <cstddef>

#define SEQ 2048
#define EMB 1024
#define HID 1024
#define G4  4096
#define VOC 50257

// ------------------------- device scratch -------------------------
__device__ __nv_bfloat16 g_xb[SEQ * EMB];            // bf16 embedded inputs
__device__ __nv_bfloat16 g_wih[G4 * EMB];            // bf16 W_ih
__device__ __nv_bfloat16 g_wout[(size_t)VOC * HID];  // bf16 W_out
__device__ __nv_bfloat16 g_hsb[SEQ * HID];           // bf16 hidden states
__device__ float g_xgates[(size_t)SEQ * G4];         // fp32 x@W_ih^T + b
__device__ float g_hbuf[2][HID];                     // double-buffered h
__device__ float g_bias[G4];                         // b_ih + b_hh
__device__ int   g_epoch;                            // published completed step
__device__ int   g_count;                            // arrival counter

// ------------------------- init -------------------------
__global__ void init_state_kernel() {
    int i = blockIdx.x * blockDim.x + threadIdx.x;
    if (i == 0) { g_epoch = 0; g_count = 0; }
    if (i < HID) { g_hbuf[0][i] = 0.f; g_hbuf[1][i] = 0.f; }
}

__global__ void bias_sum_kernel(const float* __restrict__ b_ih,
                                const float* __restrict__ b_hh) {
    int i = blockIdx.x * blockDim.x + threadIdx.x;
    if (i < G4) g_bias[i] = b_ih[i] + b_hh[i];
}

// ------------------------- converts -------------------------
__global__ void cvt_wih_kernel(const float4* __restrict__ in) {
    int i = blockIdx.x * blockDim.x + threadIdx.x;    // n4 = G4*EMB/4
    if (i >= G4 * EMB / 4) return;
    float4 v = in[i];
    __nv_bfloat162* o = (__nv_bfloat162*)g_wih;
    o[2 * i]     = __floats2bfloat162_rn(v.x, v.y);
    o[2 * i + 1] = __floats2bfloat162_rn(v.z, v.w);
}

__global__ void cvt_wout_kernel(const float4* __restrict__ in) {
    int i = blockIdx.x * blockDim.x + threadIdx.x;    // n4 = VOC*HID/4
    if (i >= (int)((size_t)VOC * HID / 4)) return;
    float4 v = in[i];
    __nv_bfloat162* o = (__nv_bfloat162*)g_wout;
    o[2 * i]     = __floats2bfloat162_rn(v.x, v.y);
    o[2 * i + 1] = __floats2bfloat162_rn(v.z, v.w);
}

__global__ void gather_emb_kernel(const int* __restrict__ seq,
                                  const float* __restrict__ emb) {
    int i = blockIdx.x * blockDim.x + threadIdx.x;    // n4 = SEQ*EMB/4
    if (i >= SEQ * EMB / 4) return;
    int t  = i >> 8;        // EMB/4 = 256 float4 per row
    int e4 = i & 255;
    float4 v = ((const float4*)(emb + (size_t)seq[t] * EMB))[e4];
    __nv_bfloat162* o = (__nv_bfloat162*)g_xb;
    o[2 * i]     = __floats2bfloat162_rn(v.x, v.y);
    o[2 * i + 1] = __floats2bfloat162_rn(v.z, v.w);
}

// ------------------------- bf16 mma GEMM: C[M,N] = A[M,K] @ B[N,K]^T + bias -------
#define GBM 128
#define GBN 64
#define GBK 32
#define GST 40   // smem row stride in bf16 (32 + 8 pad; 80B = 16B-aligned, conflict-free)

__device__ __forceinline__ void cp_async16(void* dst, const void* src) {
    uint32_t d = (uint32_t)__cvta_generic_to_shared(dst);
    asm volatile("cp.async.cg.shared.global [%0], [%1], 16;\n" :: "r"(d), "l"(src));
}
#define CP_COMMIT() asm volatile("cp.async.commit_group;\n" ::: "memory")
#define CP_WAIT0()  asm volatile("cp.async.wait_group 0;\n" ::: "memory")

__device__ __forceinline__ void mma_bf16(float* d, const uint32_t* a, const uint32_t* b) {
    asm volatile(
        "mma.sync.aligned.m16n8k16.row.col.f32.bf16.bf16.f32 "
        "{%0,%1,%2,%3}, {%4,%5,%6,%7}, {%8,%9}, {%0,%1,%2,%3};\n"
        : "+f"(d[0]), "+f"(d[1]), "+f"(d[2]), "+f"(d[3])
        : "r"(a[0]), "r"(a[1]), "r"(a[2]), "r"(a[3]), "r"(b[0]), "r"(b[1]));
}

__device__ __forceinline__ void gemm_core(
    const __nv_bfloat16* __restrict__ A,   // [M,K] row-major (M = gridDim.y*128)
    const __nv_bfloat16* __restrict__ B,   // [N,K] row-major
    const float* __restrict__ bias,        // [N]
    float* __restrict__ C,                 // [M,N]
    int N, int K)
{
    __shared__ __align__(16) __nv_bfloat16 As[2][GBM * GST];
    __shared__ __align__(16) __nv_bfloat16 Bs[2][GBN * GST];

    const int tid  = threadIdx.x;
    const int m0   = blockIdx.y * GBM;
    const int n0   = blockIdx.x * GBN;
    const int warp = tid >> 5, lane = tid & 31;
    const int wm = (warp >> 1) * 32;   // warp m-origin (0..96)
    const int wn = (warp & 1) * 32;    // warp n-origin (0 or 32)

    float acc[2][4][4];
#pragma unroll
    for (int a = 0; a < 2; a++)
#pragma unroll
        for (int b = 0; b < 4; b++)
#pragma unroll
            for (int q = 0; q < 4; q++) acc[a][b][q] = 0.f;

    const int nk = K / GBK;

    // stage loader
    auto load_stage = [&](int s, int k0) {
#pragma unroll
        for (int i = 0; i < 2; i++) {       // A: 512 x 16B chunks
            int id = tid + i * 256;
            int r = id >> 2, cc = id & 3;
            cp_async16(&As[s][r * GST + cc * 8],
                       A + (size_t)(m0 + r) * K + k0 + cc * 8);
        }
        {                                    // B: 256 x 16B chunks
            int r = tid >> 2, cc = tid & 3;
            int n = n0 + r; if (n >= N) n = N - 1;   // clamp; garbage cols never stored
            cp_async16(&Bs[s][r * GST + cc * 8],
                       B + (size_t)n * K + k0 + cc * 8);
        }
    };

    load_stage(0, 0);
    CP_COMMIT();

    for (int kt = 0; kt < nk; kt++) {
        CP_WAIT0();
        __syncthreads();
        int cur = kt & 1;
        if (kt + 1 < nk) { load_stage(cur ^ 1, (kt + 1) * GBK); CP_COMMIT(); }

#pragma unroll
        for (int kk = 0; kk < GBK; kk += 16) {
            uint32_t ra[2][4], rb[4][2];
#pragma unroll
            for (int tm = 0; tm < 2; tm++) {
                const __nv_bfloat16* ap =
                    &As[cur][(wm + tm * 16 + (lane >> 2)) * GST + kk + (lane & 3) * 2];
                ra[tm][0] = *(const uint32_t*)ap;
                ra[tm][1] = *(const uint32_t*)(ap + 8 * GST);
                ra[tm][2] = *(const uint32_t*)(ap + 8);
                ra[tm][3] = *(const uint32_t*)(ap + 8 * GST + 8);
            }
#pragma unroll
            for (int tn = 0; tn < 4; tn++) {
                const __nv_bfloat16* bp =
                    &Bs[cur][(wn + tn * 8 + (lane >> 2)) * GST + kk + (lane & 3) * 2];
                rb[tn][0] = *(const uint32_t*)bp;
                rb[tn][1] = *(const uint32_t*)(bp + 8);
            }
#pragma unroll
            for (int tm = 0; tm < 2; tm++)
#pragma unroll
                for (int tn = 0; tn < 4; tn++)
                    mma_bf16(acc[tm][tn], ra[tm], rb[tn]);
        }
    }

    // epilogue
#pragma unroll
    for (int tm = 0; tm < 2; tm++) {
#pragma unroll
        for (int tn = 0; tn < 4; tn++) {
            int r  = m0 + wm + tm * 16 + (lane >> 2);
            int cb = n0 + wn + tn * 8 + (lane & 3) * 2;
            if (cb < N) {
                C[(size_t)r * N + cb]       = acc[tm][tn][0] + bias[cb];
                C[(size_t)(r + 8) * N + cb] = acc[tm][tn][2] + bias[cb];
            }
            if (cb + 1 < N) {
                C[(size_t)r * N + cb + 1]       = acc[tm][tn][1] + bias[cb + 1];
                C[(size_t)(r + 8) * N + cb + 1] = acc[tm][tn][3] + bias[cb + 1];
            }
        }
    }
}

__global__ __launch_bounds__(256, 2) void gemm1_kernel() {
    gemm_core(g_xb, g_wih, g_bias, g_xgates, G4, EMB);
}
__global__ __launch_bounds__(256, 2) void gemm2_kernel(const float* __restrict__ b_out,
                                                       float* __restrict__ out) {
    gemm_core(g_hsb, g_wout, b_out, out, VOC, HID);
}

// ------------------------- persistent LSTM v2.1 -------------------------
// 128 CTAs x 256 threads. CTA b owns h indices j = b*8 + r, r in [0,8).
// W_hh rows (32 per CTA) live in REGISTERS as packed bf16: warp w holds rows
// rr = 4w..4w+3; lane holds k = lane*8 + 256*j (j=0..3), 8 bf16 per (row,j).
// Sync: one atomicAdd arrival per CTA + single published epoch word, polled
// with nanosleep backoff (no hot spin).
#define LSTM_NCTA    128
#define LSTM_THREADS 256

__global__ __launch_bounds__(LSTM_THREADS, 1)
void lstm_kernel(const float* __restrict__ W_hh) {
    __shared__ __align__(16) float sh[HID];   // current h (fp32)
    __shared__ float sg[32];                  // recurrent gate preacts

    const int tid = threadIdx.x, b = blockIdx.x;
    const int lane = tid & 31, w = tid >> 5;

    // ---- one-time: load this thread's weight slice into registers (bf16x2) ----
    __nv_bfloat162 wreg[4][4][4];   // [row i][chunk j][pair p]
#pragma unroll
    for (int i = 0; i < 4; i++) {
        int rr = 4 * w + i;                                   // local row 0..31
        int grow = (rr >> 3) * HID + b * 8 + (rr & 7);        // global gate row
        const float* wrow = W_hh + (size_t)grow * HID;
#pragma unroll
        for (int j = 0; j < 4; j++) {
            int k = lane * 8 + j * 256;
            float4 a = *(const float4*)(wrow + k);
            float4 c = *(const float4*)(wrow + k + 4);
            wreg[i][j][0] = __floats2bfloat162_rn(a.x, a.y);
            wreg[i][j][1] = __floats2bfloat162_rn(a.z, a.w);
            wreg[i][j][2] = __floats2bfloat162_rn(c.x, c.y);
            wreg[i][j][3] = __floats2bfloat162_rn(c.z, c.w);
        }
    }

    float c_reg = 0.f;   // thread r<8 carries c for unit j = b*8 + r
    __syncthreads();

    for (int t = 0; t < SEQ; t++) {
        // prefetch x-gate contributions (independent of h) before polling
        float xg0 = 0.f, xg1 = 0.f, xg2 = 0.f, xg3 = 0.f;
        if (tid < 8) {
            const float* xgp = g_xgates + (size_t)t * G4 + b * 8 + tid;
            xg0 = xgp[0]; xg1 = xgp[1024]; xg2 = xgp[2048]; xg3 = xgp[3072];
        }

        // wait: all CTAs finished step t-1 (single-word epoch poll by tid 0,
        // L2-scoped load + nanosleep backoff)
        if (t > 0) {
            if (tid == 0) {
                while (__ldcg((const int*)&g_epoch) < t) { __nanosleep(40); }
                __threadfence();   // acquire; propagated CTA-wide by the barrier
            }
            __syncthreads();
        }

        // load current h from L2 (ldcg: never L1-cached, always coherent)
        {
            const float4* hg4 = (const float4*)g_hbuf[t & 1];
            float4 v = __ldcg(hg4 + tid);
            ((float4*)sh)[tid] = v;
        }
        __syncthreads();

        // recurrent dots: warp w computes rows 4w..4w+3 (fp32 accumulate)
        {
            float acc0 = 0.f, acc1 = 0.f, acc2 = 0.f, acc3 = 0.f;
#pragma unroll
            for (int j = 0; j < 4; j++) {
                int k = lane * 8 + j * 256;
                float4 h0 = *(const float4*)(sh + k);
                float4 h1 = *(const float4*)(sh + k + 4);
#pragma unroll
                for (int i = 0; i < 4; i++) {
                    float2 p0 = __bfloat1622float2(wreg[i][j][0]);
                    float2 p1 = __bfloat1622float2(wreg[i][j][1]);
                    float2 p2 = __bfloat1622float2(wreg[i][j][2]);
                    float2 p3 = __bfloat1622float2(wreg[i][j][3]);
                    float s;
                    s = fmaf(p0.x, h0.x, fmaf(p0.y, h0.y,
                        fmaf(p1.x, h0.z, fmaf(p1.y, h0.w,
                        fmaf(p2.x, h1.x, fmaf(p2.y, h1.y,
                        fmaf(p3.x, h1.z, p3.y * h1.w)))))));
                    if (i == 0) acc0 += s;
                    else if (i == 1) acc1 += s;
                    else if (i == 2) acc2 += s;
                    else acc3 += s;
                }
            }
#pragma unroll
            for (int o = 16; o > 0; o >>= 1) {
                acc0 += __shfl_xor_sync(0xffffffffu, acc0, o);
                acc1 += __shfl_xor_sync(0xffffffffu, acc1, o);
                acc2 += __shfl_xor_sync(0xffffffffu, acc2, o);
                acc3 += __shfl_xor_sync(0xffffffffu, acc3, o);
            }
            if (lane == 0) {
                sg[4 * w + 0] = acc0; sg[4 * w + 1] = acc1;
                sg[4 * w + 2] = acc2; sg[4 * w + 3] = acc3;
            }
        }
        __syncthreads();

        // elementwise gate update for the 8 owned units
        if (tid < 8) {
            int j = b * 8 + tid;
            float gi = sg[0 + tid]  + xg0;
            float gf = sg[8 + tid]  + xg1;
            float gg = sg[16 + tid] + xg2;
            float go = sg[24 + tid] + xg3;
            float i_ = 1.f / (1.f + expf(-gi));
            float f_ = 1.f / (1.f + expf(-gf));
            float g_ = tanhf(gg);
            float o_ = 1.f / (1.f + expf(-go));
            c_reg = f_ * c_reg + i_ * g_;
            float h_ = o_ * tanhf(c_reg);
            g_hbuf[(t + 1) & 1][j] = h_;
            g_hsb[(size_t)t * HID + j] = __float2bfloat16(h_);
        }
        __syncthreads();                       // order h stores before arrival

        // arrive; last CTA publishes the epoch
        if (tid == 0) {
            __threadfence();                   // release h stores (cumulative)
            int old = atomicAdd(&g_count, 1);
            if (old == (t + 1) * LSTM_NCTA - 1) {
                __threadfence();
                *(volatile int*)&g_epoch = t + 1;
            }
        }
    }
}

// ------------------------- row log-softmax (in place) -------------------------
__global__ void logsoftmax_kernel(float* __restrict__ out, int N) {
    const int row = blockIdx.x;
    float* p = out + (size_t)row * N;
    const int tid = threadIdx.x, lane = tid & 31, wid = tid >> 5;
    const int nt = blockDim.x, nw = nt >> 5;
    __shared__ float red[16];

    float m = -3.4e38f;
    for (int i = tid; i < N; i += nt) m = fmaxf(m, p[i]);
#pragma unroll
    for (int o = 16; o > 0; o >>= 1) m = fmaxf(m, __shfl_xor_sync(0xffffffffu, m, o));
    if (lane == 0) red[wid] = m;
    __syncthreads();
    if (tid == 0) {
        float v = red[0];
        for (int i = 1; i < nw; i++) v = fmaxf(v, red[i]);
        red[0] = v;
    }
    __syncthreads();
    m = red[0];
    __syncthreads();

    float s = 0.f;
    for (int i = tid; i < N; i += nt) s += __expf(p[i] - m);
#pragma unroll
    for (int o = 16; o > 0; o >>= 1) s += __shfl_xor_sync(0xffffffffu, s, o);
    if (lane == 0) red[wid] = s;
    __syncthreads();
    if (tid == 0) {
        float v = 0.f;
        for (int i = 0; i < nw; i++) v += red[i];
        red[0] = v;
    }
    __syncthreads();
    float lse = m + logf(red[0]);

    for (int i = tid; i < N; i += nt) p[i] -= lse;
}

// ------------------------- launch -------------------------
extern "C" void kernel_launch(void* const* d_in, const int* in_sizes, int n_in,
                              void* d_out, int out_size) {
    const int*   seq   = (const int*)d_in[0];
    const float* emb   = (const float*)d_in[1];
    const float* W_ih  = (const float*)d_in[2];
    const float* W_hh  = (const float*)d_in[3];
    const float* b_ih  = (const float*)d_in[4];
    const float* b_hh  = (const float*)d_in[5];
    const float* W_out = (const float*)d_in[6];
    const float* b_out = (const float*)d_in[7];
    float* out = (float*)d_out;

    (void)in_sizes; (void)n_in; (void)out_size;

    init_state_kernel<<<4, 256>>>();
    bias_sum_kernel<<<16, 256>>>(b_ih, b_hh);
    cvt_wih_kernel<<<(G4 * EMB / 4) / 256, 256>>>((const float4*)W_ih);
    cvt_wout_kernel<<<(int)(((size_t)VOC * HID / 4 + 255) / 256), 256>>>((const float4*)W_out);
    gather_emb_kernel<<<(SEQ * EMB / 4) / 256, 256>>>(seq, emb);

    {   // x_gates = xb @ W_ih^T + (b_ih + b_hh)
        dim3 grid(G4 / GBN, SEQ / GBM);
        gemm1_kernel<<<grid, 256>>>();
    }

    lstm_kernel<<<LSTM_NCTA, LSTM_THREADS>>>(W_hh);

    {   // logits = hs @ W_out^T + b_out  -> d_out
        dim3 grid((VOC + GBN - 1) / GBN, SEQ / GBM);
        gemm2_kernel<<<grid, 256>>>(b_out, out);
    }

    logsoftmax_kernel<<<SEQ, 512>>>(out, VOC);
}